// round 6
// baseline (speedup 1.0000x reference)
#include <cuda_runtime.h>

#define BB 64
#define SS 4096
#define DD 128
#define NPTS (BB*SS)
#define CHUNKS 16
#define PPB (SS/CHUNKS)
#define GRID_STATS 740            // 5 blocks/SM * 148 SMs, one wave
#define NW_STATS (GRID_STATS * 8)
#define GRID_FO 888               // 6 blocks/SM * 148 SMs, one wave
#define NW_FO (GRID_FO * 8)
#define GRID_FG 592               // 4 blocks/SM, general fallback
#define NW_FG (GRID_FG * 8)

// scratch (allocation-free rule: __device__ globals)
__device__ float    g_part[CHUNKS*BB*DD]; // per-(chunk,b,d) partial sums
__device__ float4   g_mean4[DD/4];        // global Lorentz centroid
__device__ double   g_fs[DD];             // per-feature sum of x_T
__device__ double   g_fq[DD];             // per-feature sum of x_T^2
__device__ unsigned g_ctr;                // last-block-done counter (reset each use)

__device__ __forceinline__ float wsum(float v) {
#pragma unroll
    for (int o = 16; o; o >>= 1) v += __shfl_xor_sync(0xffffffffu, v, o);
    return v;
}

template<int P>
__device__ __forceinline__ void wsumP(float* v) {
#pragma unroll
    for (int o = 16; o; o >>= 1) {
        float t[P];
#pragma unroll
        for (int i = 0; i < P; i++) t[i] = __shfl_xor_sync(0xffffffffu, v[i], o);
#pragma unroll
        for (int i = 0; i < P; i++) v[i] += t[i];
    }
}

// Pass 1: per-(b,chunk) sums; last block to finish computes the centroid.
__global__ __launch_bounds__(256) void k_sumS(const float4* __restrict__ x4) {
    int b     = blockIdx.x >> 4;
    int chunk = blockIdx.x & 15;
    int tid = threadIdx.x;
    int warp = tid >> 5, lane = tid & 31;
    const float4* base = x4 + ((size_t)b * SS + (size_t)chunk * PPB) * 32 + lane;
    float4 acc = make_float4(0.f, 0.f, 0.f, 0.f);
#pragma unroll 4
    for (int s = warp; s < PPB; s += 8) {
        float4 v = base[(size_t)s * 32];
        acc.x += v.x; acc.y += v.y; acc.z += v.z; acc.w += v.w;
    }
    __shared__ float sh[8 * 128];
    int o = warp * 128 + lane * 4;
    sh[o] = acc.x; sh[o+1] = acc.y; sh[o+2] = acc.z; sh[o+3] = acc.w;
    __syncthreads();
    if (tid < 128) {
        float v = 0.f;
#pragma unroll
        for (int w = 0; w < 8; w++) v += sh[w * 128 + tid];
        g_part[(chunk * BB + b) * DD + tid] = v;
    }

    // ---- last-block-done: fused centroid ----
    __shared__ bool s_last;
    __threadfence();
    __syncthreads();
    if (tid == 0) {
        unsigned n = atomicAdd(&g_ctr, 1u);
        s_last = (n == gridDim.x - 1);
    }
    __syncthreads();
    if (!s_last) return;
    if (tid == 0) g_ctr = 0;                    // reset for graph replay

    __shared__ float sh1[BB * DD];              // 32 KB
    __shared__ float red[128];
    __shared__ float s_linner;

    // sum the 16 chunk partials for each (b,d)
    for (int idx = tid; idx < BB*DD; idx += 256) {
        float s = 0.f;
#pragma unroll
        for (int c = 0; c < CHUNKS; c++) s += g_part[c * BB * DD + idx];
        sh1[idx] = s;
    }
    if (tid < DD) { g_fs[tid] = 0.0; g_fq[tid] = 0.0; }
    __syncthreads();

    // normalize each batch-mean onto the hyperboloid (8 warps x 8 reps)
#pragma unroll
    for (int rep = 0; rep < 8; rep++) {
        int bb = warp + rep * 8;
        float a[4];
        float lc = 0.f;
#pragma unroll
        for (int j = 0; j < 4; j++) {
            a[j] = sh1[bb * 128 + lane * 4 + j] * (1.f / SS);
            float c = a[j] * a[j];
            if (lane == 0 && j == 0) c = -c;
            lc += c;
        }
        lc = wsum(lc);
        float denom = sqrtf(fmaxf(-lc, 1e-8f));
#pragma unroll
        for (int j = 0; j < 4; j++) sh1[bb * 128 + lane * 4 + j] = a[j] / denom;
    }
    __syncthreads();

    // mean of the 64 centroids, renormalize
    float a2 = 0.f;
    if (tid < 128) {
        float s = 0.f;
        for (int bb = 0; bb < BB; bb++) s += sh1[bb * 128 + tid];
        a2 = s * (1.f / BB);
        float c = a2 * a2;
        red[tid] = (tid == 0) ? -c : c;
    }
    __syncthreads();
    for (int off = 64; off > 0; off >>= 1) {
        if (tid < off && tid + off < 128) red[tid] += red[tid + off];
        __syncthreads();
    }
    if (tid == 0) s_linner = red[0];
    __syncthreads();
    if (tid < 128) {
        float denom2 = sqrtf(fmaxf(-s_linner, 1e-8f));
        ((float*)g_mean4)[tid] = a2 / denom2;
    }
}

// x_T for P points: logmap at mean + transport to origin. ONE warp reduction.
// linner(u,u) = alpha^2 - 1; acosh(a) = log(a+sqrt(a^2-1)); result time comp == 0.
template<int P>
__device__ __forceinline__ void xT_P(float4* v, const float4 m, const float mxs,
                                     const float m0, const float inv1pm0,
                                     const float e0) {
    float dp[P];
#pragma unroll
    for (int i = 0; i < P; i++)
        dp[i] = v[i].x*mxs + v[i].y*m.y + v[i].z*m.z + v[i].w*m.w;  // -> linner(x,m)
    wsumP<P>(dp);
    float x0[P];
#pragma unroll
    for (int i = 0; i < P; i++) x0[i] = __shfl_sync(0xffffffffu, v[i].x, 0);
#pragma unroll
    for (int i = 0; i < P; i++) {
        float alpha  = fmaxf(-dp[i], 1.0f + 1e-7f);
        float uu     = fmaf(alpha, alpha, -1.0f);           // linner(u,u)
        float runorm = rsqrtf(uu);
        float unorm  = uu * runorm;
        float fac    = __logf(alpha + unorm) * runorm;      // acosh(a)/|u|
        float u0     = fmaf(-alpha, m0, x0[i]);
        float coef   = -fac * u0 * inv1pm0;                 // transp0back
        float c2     = fmaf(-fac, alpha, coef);             // t = fac*x + c2*m + coef*o
        float4 t;
        t.x = fmaf(fac, v[i].x, fmaf(c2, m.x, coef * e0));
        t.y = fmaf(fac, v[i].y, c2 * m.y);
        t.z = fmaf(fac, v[i].z, c2 * m.z);
        t.w = fmaf(fac, v[i].w, c2 * m.w);
        v[i] = t;
    }
}

// Pass 3: per-feature sum / sumsq of x_T (reverse sweep, 5 blocks/SM, no spills)
__global__ __launch_bounds__(256, 5) void k_stats(const float4* __restrict__ x4) {
    constexpr int P = 2;
    constexpr int PIT = NPTS / P;
    int warp = threadIdx.x >> 5, lane = threadIdx.x & 31;
    float4 m = g_mean4[lane];
    float m0 = __shfl_sync(0xffffffffu, m.x, 0);
    float inv1pm0 = 1.f / (1.f + m0);
    float mxs = (lane == 0) ? -m.x : m.x;
    float e0  = (lane == 0) ?  1.f : 0.f;
    float4 ss = make_float4(0,0,0,0), sq = make_float4(0,0,0,0);
    int gw = blockIdx.x * 8 + warp;

    for (int p = PIT - 1 - gw; p >= 0; p -= NW_STATS) {   // reverse sweep
        unsigned bi = (unsigned)p * 64u + lane;
        float4 v[P];
        v[0] = x4[bi];
        v[1] = x4[bi + 32u];
        xT_P<P>(v, m, mxs, m0, inv1pm0, e0);
#pragma unroll
        for (int i = 0; i < P; i++) {
            ss.x += v[i].x; ss.y += v[i].y; ss.z += v[i].z; ss.w += v[i].w;
            sq.x = fmaf(v[i].x, v[i].x, sq.x); sq.y = fmaf(v[i].y, v[i].y, sq.y);
            sq.z = fmaf(v[i].z, v[i].z, sq.z); sq.w = fmaf(v[i].w, v[i].w, sq.w);
        }
    }
    __shared__ float shs[8 * 128];
    __shared__ float shq[8 * 128];
    int o = warp * 128 + lane * 4;
    shs[o]=ss.x; shs[o+1]=ss.y; shs[o+2]=ss.z; shs[o+3]=ss.w;
    shq[o]=sq.x; shq[o+1]=sq.y; shq[o+2]=sq.z; shq[o+3]=sq.w;
    __syncthreads();
    if (threadIdx.x < 128) {
        float a = 0.f, b = 0.f;
#pragma unroll
        for (int w = 0; w < 8; w++) { a += shs[w*128 + threadIdx.x]; b += shq[w*128 + threadIdx.x]; }
        atomicAdd(&g_fs[threadIdx.x], (double)a);
        atomicAdd(&g_fq[threadIdx.x], (double)b);
    }
}

// per-feature scale = gamma / (sqrt(var + eps) + eps)
__device__ __forceinline__ float4 load_scale(const float4* gamma4, int lane) {
    float4 g = gamma4[lane];
    float gv[4] = {g.x, g.y, g.z, g.w};
    float sv[4];
#pragma unroll
    for (int j = 0; j < 4; j++) {
        int d = lane * 4 + j;
        float mv  = (float)(g_fs[d] * (1.0 / NPTS));
        float var = (float)(g_fq[d] * (1.0 / NPTS)) - mv * mv;
        float std = sqrtf(fmaxf(var, 0.f) + 1e-5f);
        sv[j] = gv[j] / (std + 1e-5f);
    }
    return make_float4(sv[0], sv[1], sv[2], sv[3]);
}

// Pass 4 (hot path): beta == origin. transp0 = identity; one reduction per point.
__global__ __launch_bounds__(256, 6) void k_final_o(const float4* __restrict__ x4,
                                                    const float4* __restrict__ gamma4,
                                                    const float4* __restrict__ beta4,
                                                    float4* __restrict__ out4) {
    constexpr int P = 2;
    constexpr int PIT = NPTS / P;
    int warp = threadIdx.x >> 5, lane = threadIdx.x & 31;
    float4 be = beta4[lane];
    float b0  = __shfl_sync(0xffffffffu, be.x, 0);
    float bsq = wsum(be.x*be.x + be.y*be.y + be.z*be.z + be.w*be.w);
    if (!((b0 == 1.0f) && (bsq - b0 * b0 <= 0.0f))) return;   // not origin -> k_final_g

    float4 m = g_mean4[lane];
    float m0 = __shfl_sync(0xffffffffu, m.x, 0);
    float inv1pm0 = 1.f / (1.f + m0);
    float mxs = (lane == 0) ? -m.x : m.x;
    float e0  = (lane == 0) ?  1.f : 0.f;
    float4 scl = load_scale(gamma4, lane);

    int gw = blockIdx.x * 8 + warp;
    for (int p = gw; p < PIT; p += NW_FO) {       // forward sweep (k_stats L2 tail)
        unsigned bi = (unsigned)p * 64u + lane;
        float4 v[P];
        v[0] = __ldcs(&x4[bi]);
        v[1] = __ldcs(&x4[bi + 32u]);
        xT_P<P>(v, m, mxs, m0, inv1pm0, e0);
        float re[P];
#pragma unroll
        for (int i = 0; i < P; i++) {
            v[i].x *= scl.x; v[i].y *= scl.y; v[i].z *= scl.z; v[i].w *= scl.w;
            float4 t = v[i];
            re[i] = t.x*t.x + t.y*t.y + t.z*t.z + t.w*t.w;
        }
        wsumP<P>(re);
#pragma unroll
        for (int i = 0; i < P; i++) {
            float rre = fmaxf(re[i], 1e-8f);
            float rq  = rsqrtf(rre);
            float en  = rre * rq;                  // ||t||
            float nu  = fminf(en, 32.f);           // esc * ||t||
            float ex  = __expf(nu);
            float exi = __expf(-nu);
            float ch  = 0.5f * (ex + exi);
            float sf  = 0.5f * (ex - exi) / en;    // esc * sinh(nu)/nu
            float4 t = v[i], o;
            o.x = fmaf(sf, t.x, ch * e0);
            o.y = sf * t.y;
            o.z = sf * t.z;
            o.w = sf * t.w;
            __stcs(&out4[bi + (unsigned)i * 32u], o);
        }
    }
}

// Pass 4 (general fallback): arbitrary beta on the hyperboloid.
__global__ __launch_bounds__(256) void k_final_g(const float4* __restrict__ x4,
                                                 const float4* __restrict__ gamma4,
                                                 const float4* __restrict__ beta4,
                                                 float4* __restrict__ out4) {
    constexpr int P = 2;
    constexpr int PIT = NPTS / P;
    int warp = threadIdx.x >> 5, lane = threadIdx.x & 31;
    float4 be = beta4[lane];
    float b0  = __shfl_sync(0xffffffffu, be.x, 0);
    float bsq = wsum(be.x*be.x + be.y*be.y + be.z*be.z + be.w*be.w);
    if ((b0 == 1.0f) && (bsq - b0 * b0 <= 0.0f)) return;      // origin -> k_final_o

    float4 m = g_mean4[lane];
    float m0 = __shfl_sync(0xffffffffu, m.x, 0);
    float inv1pm0 = 1.f / (1.f + m0);
    float mxs = (lane == 0) ? -m.x : m.x;
    float e0  = (lane == 0) ?  1.f : 0.f;
    float4 scl = load_scale(gamma4, lane);
    float inv1pb0 = 1.f / (1.f + b0);
    float bxs = (lane == 0) ? -be.x : be.x;

    int gw = blockIdx.x * 8 + warp;
    for (int p = gw; p < PIT; p += NW_FG) {
        unsigned bi = (unsigned)p * 64u + lane;
        float4 v[P];
        v[0] = __ldcs(&x4[bi]);
        v[1] = __ldcs(&x4[bi + 32u]);
        xT_P<P>(v, m, mxs, m0, inv1pm0, e0);
        float r2[2 * P];
#pragma unroll
        for (int i = 0; i < P; i++) {
            v[i].x *= scl.x; v[i].y *= scl.y; v[i].z *= scl.z; v[i].w *= scl.w;
            float4 t = v[i];
            r2[2*i]   = t.x*t.x + t.y*t.y + t.z*t.z + t.w*t.w;
            r2[2*i+1] = t.x*bxs + t.y*be.y + t.z*be.z + t.w*be.w;   // linner(t,be)
        }
        wsumP<2 * P>(r2);
#pragma unroll
        for (int i = 0; i < P; i++) {
            float rre = fmaxf(r2[2*i], 1e-8f);
            float rq  = rsqrtf(rre);
            float esc = fminf(1.f, 32.f * rq);     // euclid cap
            float coef = esc * r2[2*i+1] * inv1pb0;
            float4 t = v[i], w;
            w.x = fmaf(coef, be.x + e0, esc * t.x);
            w.y = fmaf(coef, be.y, esc * t.y);
            w.z = fmaf(coef, be.z, esc * t.z);
            w.w = fmaf(coef, be.w, esc * t.w);
            // linner(w,w) = esc^2 * re   (t0 == 0; transport preserves norm)
            float nu  = fminf(rre * rq, 32.f);
            float rnu = fmaxf(nu, 1e-4f);
            float ex  = __expf(rnu);
            float exi = __expf(-rnu);
            float ch  = 0.5f * (ex + exi);
            float shn = 0.5f * (ex - exi) / rnu;
            float4 o;
            o.x = fmaf(ch, be.x, shn * w.x);
            o.y = fmaf(ch, be.y, shn * w.y);
            o.z = fmaf(ch, be.z, shn * w.z);
            o.w = fmaf(ch, be.w, shn * w.w);
            __stcs(&out4[bi + (unsigned)i * 32u], o);
        }
    }
}

extern "C" void kernel_launch(void* const* d_in, const int* in_sizes, int n_in,
                              void* d_out, int out_size) {
    const float4* x  = (const float4*)d_in[0];
    const float4* ga = (const float4*)d_in[1];
    const float4* be = (const float4*)d_in[2];
    float4* out = (float4*)d_out;
    (void)in_sizes; (void)n_in; (void)out_size;

    k_sumS<<<BB * CHUNKS, 256>>>(x);           // includes fused centroid
    k_stats<<<GRID_STATS, 256>>>(x);
    k_final_o<<<GRID_FO, 256>>>(x, ga, be, out);
    k_final_g<<<GRID_FG, 256>>>(x, ga, be, out);
}

// round 7
// speedup vs baseline: 1.1054x; 1.1054x over previous
#include <cuda_runtime.h>

#define BB 64
#define SS 4096
#define DD 128
#define NPTS (BB*SS)
#define CHUNKS 16
#define PPB (SS/CHUNKS)
#define GRID_STATS 888            // 6 blocks/SM * 148 SMs, one wave
#define NW_STATS (GRID_STATS * 8)
#define GRID_FO 740               // 5 blocks/SM * 148 SMs, one wave
#define NW_FO (GRID_FO * 8)
#define GRID_FG 592               // 4 blocks/SM, general fallback
#define NW_FG (GRID_FG * 8)

// scratch (allocation-free rule: __device__ globals)
__device__ float    g_part[CHUNKS*BB*DD]; // per-(chunk,b,d) partial sums
__device__ float4   g_mean4[DD/4];        // global Lorentz centroid
__device__ double   g_fs[DD];             // per-feature sum of x_T
__device__ double   g_fq[DD];             // per-feature sum of x_T^2
__device__ int      g_is_origin;          // beta == (1,0,...,0)?

__device__ __forceinline__ float wsum(float v) {
#pragma unroll
    for (int o = 16; o; o >>= 1) v += __shfl_xor_sync(0xffffffffu, v, o);
    return v;
}

template<int P>
__device__ __forceinline__ void wsumP(float* v) {
#pragma unroll
    for (int o = 16; o; o >>= 1) {
        float t[P];
#pragma unroll
        for (int i = 0; i < P; i++) t[i] = __shfl_xor_sync(0xffffffffu, v[i], o);
#pragma unroll
        for (int i = 0; i < P; i++) v[i] += t[i];
    }
}

// Pass 1: per-(b,chunk) sums over 256 points -> g_part (no atomics, no init)
__global__ __launch_bounds__(256) void k_sumS(const float4* __restrict__ x4) {
    int b     = blockIdx.x >> 4;
    int chunk = blockIdx.x & 15;
    int warp = threadIdx.x >> 5, lane = threadIdx.x & 31;
    const float4* base = x4 + ((size_t)b * SS + (size_t)chunk * PPB) * 32 + lane;
    float4 acc = make_float4(0.f, 0.f, 0.f, 0.f);
#pragma unroll 4
    for (int s = warp; s < PPB; s += 8) {
        float4 v = base[(size_t)s * 32];
        acc.x += v.x; acc.y += v.y; acc.z += v.z; acc.w += v.w;
    }
    __shared__ float sh[8 * 128];
    int o = warp * 128 + lane * 4;
    sh[o] = acc.x; sh[o+1] = acc.y; sh[o+2] = acc.z; sh[o+3] = acc.w;
    __syncthreads();
    if (threadIdx.x < 128) {
        float v = 0.f;
#pragma unroll
        for (int w = 0; w < 8; w++) v += sh[w * 128 + threadIdx.x];
        g_part[(chunk * BB + b) * DD + threadIdx.x] = v;
    }
}

// Pass 2 (tiny): reduce partials, centroid of centroids, zero stats, beta flag
__global__ __launch_bounds__(1024) void k_centroid(const float4* __restrict__ beta4) {
    __shared__ float sh1[BB * DD];
    __shared__ float red[128];
    __shared__ float s_linner;
    int tid = threadIdx.x, warp = tid >> 5, lane = tid & 31;

    // phase 1: sum the 16 chunk partials for each (b,d)
    for (int idx = tid; idx < BB*DD; idx += 1024) {
        float s = 0.f;
#pragma unroll
        for (int c = 0; c < CHUNKS; c++) s += g_part[c * BB * DD + idx];
        sh1[idx] = s;
    }
    if (tid < DD) { g_fs[tid] = 0.0; g_fq[tid] = 0.0; }

    // beta-origin flag (warp 31, doesn't touch sh1)
    if (warp == 31) {
        float4 be = beta4[lane];
        float b0  = __shfl_sync(0xffffffffu, be.x, 0);
        float bsq = wsum(be.x*be.x + be.y*be.y + be.z*be.z + be.w*be.w);
        if (lane == 0) g_is_origin = ((b0 == 1.0f) && (bsq - b0 * b0 <= 0.0f)) ? 1 : 0;
    }
    __syncthreads();

    // phase 2: normalize each batch-mean onto the hyperboloid
#pragma unroll
    for (int rep = 0; rep < 2; rep++) {
        int b = warp + rep * 32;
        float a[4];
        float lc = 0.f;
#pragma unroll
        for (int j = 0; j < 4; j++) {
            a[j] = sh1[b * 128 + lane * 4 + j] * (1.f / SS);
            float c = a[j] * a[j];
            if (lane == 0 && j == 0) c = -c;
            lc += c;
        }
        lc = wsum(lc);
        float denom = sqrtf(fmaxf(-lc, 1e-8f));
#pragma unroll
        for (int j = 0; j < 4; j++) sh1[b * 128 + lane * 4 + j] = a[j] / denom;
    }
    __syncthreads();

    // phase 3: mean of the 64 centroids, renormalize
    float a2 = 0.f;
    if (tid < 128) {
        float s = 0.f;
        for (int b = 0; b < BB; b++) s += sh1[b * 128 + tid];
        a2 = s * (1.f / BB);
        float c = a2 * a2;
        red[tid] = (tid == 0) ? -c : c;
    }
    __syncthreads();
    for (int off = 64; off > 0; off >>= 1) {
        if (tid < off) red[tid] += red[tid + off];
        __syncthreads();
    }
    if (tid == 0) s_linner = red[0];
    __syncthreads();
    if (tid < 128) {
        float denom2 = sqrtf(fmaxf(-s_linner, 1e-8f));
        ((float*)g_mean4)[tid] = a2 / denom2;
    }
}

// x_T for P points: logmap at mean + transport to origin. ONE warp reduction.
// linner(u,u) = alpha^2 - 1; acosh(a) = log(a+sqrt(a^2-1)); result time comp == 0.
template<int P>
__device__ __forceinline__ void xT_P(float4* v, const float4 m, const float mxs,
                                     const float m0, const float inv1pm0,
                                     const float e0) {
    float dp[P];
#pragma unroll
    for (int i = 0; i < P; i++)
        dp[i] = v[i].x*mxs + v[i].y*m.y + v[i].z*m.z + v[i].w*m.w;  // -> linner(x,m)
    wsumP<P>(dp);
    float x0[P];
#pragma unroll
    for (int i = 0; i < P; i++) x0[i] = __shfl_sync(0xffffffffu, v[i].x, 0);
#pragma unroll
    for (int i = 0; i < P; i++) {
        float alpha  = fmaxf(-dp[i], 1.0f + 1e-7f);
        float uu     = fmaf(alpha, alpha, -1.0f);           // linner(u,u)
        float runorm = rsqrtf(uu);
        float unorm  = uu * runorm;
        float fac    = __logf(alpha + unorm) * runorm;      // acosh(a)/|u|
        float u0     = fmaf(-alpha, m0, x0[i]);
        float coef   = -fac * u0 * inv1pm0;                 // transp0back
        float c2     = fmaf(-fac, alpha, coef);             // t = fac*x + c2*m + coef*o
        float4 t;
        t.x = fmaf(fac, v[i].x, fmaf(c2, m.x, coef * e0));
        t.y = fmaf(fac, v[i].y, c2 * m.y);
        t.z = fmaf(fac, v[i].z, c2 * m.z);
        t.w = fmaf(fac, v[i].w, c2 * m.w);
        v[i] = t;
    }
}

// Pass 3: per-feature sum / sumsq of x_T (reverse sweep, 6 blocks/SM)
__global__ __launch_bounds__(256, 6) void k_stats(const float4* __restrict__ x4) {
    constexpr int P = 2;
    constexpr int PIT = NPTS / P;
    int warp = threadIdx.x >> 5, lane = threadIdx.x & 31;
    float4 m = g_mean4[lane];
    float m0 = __shfl_sync(0xffffffffu, m.x, 0);
    float inv1pm0 = 1.f / (1.f + m0);
    float mxs = (lane == 0) ? -m.x : m.x;
    float e0  = (lane == 0) ?  1.f : 0.f;
    float4 ss = make_float4(0,0,0,0), sq = make_float4(0,0,0,0);
    int gw = blockIdx.x * 8 + warp;

    for (int p = PIT - 1 - gw; p >= 0; p -= NW_STATS) {   // reverse sweep
        unsigned bi = (unsigned)p * 64u + lane;
        float4 v[P];
        v[0] = x4[bi];
        v[1] = x4[bi + 32u];
        xT_P<P>(v, m, mxs, m0, inv1pm0, e0);
#pragma unroll
        for (int i = 0; i < P; i++) {
            ss.x += v[i].x; ss.y += v[i].y; ss.z += v[i].z; ss.w += v[i].w;
            sq.x = fmaf(v[i].x, v[i].x, sq.x); sq.y = fmaf(v[i].y, v[i].y, sq.y);
            sq.z = fmaf(v[i].z, v[i].z, sq.z); sq.w = fmaf(v[i].w, v[i].w, sq.w);
        }
    }
    __shared__ float shs[8 * 128];
    __shared__ float shq[8 * 128];
    int o = warp * 128 + lane * 4;
    shs[o]=ss.x; shs[o+1]=ss.y; shs[o+2]=ss.z; shs[o+3]=ss.w;
    shq[o]=sq.x; shq[o+1]=sq.y; shq[o+2]=sq.z; shq[o+3]=sq.w;
    __syncthreads();
    if (threadIdx.x < 128) {
        float a = 0.f, b = 0.f;
#pragma unroll
        for (int w = 0; w < 8; w++) { a += shs[w*128 + threadIdx.x]; b += shq[w*128 + threadIdx.x]; }
        atomicAdd(&g_fs[threadIdx.x], (double)a);
        atomicAdd(&g_fq[threadIdx.x], (double)b);
    }
}

// per-feature scale = gamma / (sqrt(var + eps) + eps)
__device__ __forceinline__ float4 load_scale(const float4* gamma4, int lane) {
    float4 g = gamma4[lane];
    float gv[4] = {g.x, g.y, g.z, g.w};
    float sv[4];
#pragma unroll
    for (int j = 0; j < 4; j++) {
        int d = lane * 4 + j;
        float mv  = (float)(g_fs[d] * (1.0 / NPTS));
        float var = (float)(g_fq[d] * (1.0 / NPTS)) - mv * mv;
        float std = sqrtf(fmaxf(var, 0.f) + 1e-5f);
        sv[j] = gv[j] / (std + 1e-5f);
    }
    return make_float4(sv[0], sv[1], sv[2], sv[3]);
}

// Pass 4 (hot path): beta == origin. transp0 = identity; one reduction per point.
__global__ __launch_bounds__(256, 5) void k_final_o(const float4* __restrict__ x4,
                                                    const float4* __restrict__ gamma4,
                                                    float4* __restrict__ out4) {
    if (!g_is_origin) return;                     // fallback kernel handles it
    constexpr int P = 2;
    constexpr int PIT = NPTS / P;
    int warp = threadIdx.x >> 5, lane = threadIdx.x & 31;
    float4 m = g_mean4[lane];
    float m0 = __shfl_sync(0xffffffffu, m.x, 0);
    float inv1pm0 = 1.f / (1.f + m0);
    float mxs = (lane == 0) ? -m.x : m.x;
    float e0  = (lane == 0) ?  1.f : 0.f;
    float4 scl = load_scale(gamma4, lane);

    int gw = blockIdx.x * 8 + warp;
    for (int p = gw; p < PIT; p += NW_FO) {       // forward sweep (k_stats L2 tail)
        unsigned bi = (unsigned)p * 64u + lane;
        float4 v[P];
        v[0] = __ldcs(&x4[bi]);
        v[1] = __ldcs(&x4[bi + 32u]);
        xT_P<P>(v, m, mxs, m0, inv1pm0, e0);
        float re[P];
#pragma unroll
        for (int i = 0; i < P; i++) {
            v[i].x *= scl.x; v[i].y *= scl.y; v[i].z *= scl.z; v[i].w *= scl.w;
            float4 t = v[i];
            re[i] = t.x*t.x + t.y*t.y + t.z*t.z + t.w*t.w;
        }
        wsumP<P>(re);
#pragma unroll
        for (int i = 0; i < P; i++) {
            float rre = fmaxf(re[i], 1e-8f);
            float rq  = rsqrtf(rre);
            float en  = rre * rq;                  // ||t||
            float nu  = fminf(en, 32.f);           // esc * ||t||
            float ex  = __expf(nu);
            float exi = __expf(-nu);
            float ch  = 0.5f * (ex + exi);
            float sf  = 0.5f * (ex - exi) / en;    // esc * sinh(nu)/nu
            float4 t = v[i], o;
            o.x = fmaf(sf, t.x, ch * e0);
            o.y = sf * t.y;
            o.z = sf * t.z;
            o.w = sf * t.w;
            __stcs(&out4[bi + (unsigned)i * 32u], o);
        }
    }
}

// Pass 4 (general fallback): arbitrary beta on the hyperboloid.
__global__ __launch_bounds__(256) void k_final_g(const float4* __restrict__ x4,
                                                 const float4* __restrict__ gamma4,
                                                 const float4* __restrict__ beta4,
                                                 float4* __restrict__ out4) {
    if (g_is_origin) return;                      // hot-path kernel handled it
    constexpr int P = 2;
    constexpr int PIT = NPTS / P;
    int warp = threadIdx.x >> 5, lane = threadIdx.x & 31;
    float4 be = beta4[lane];
    float b0  = __shfl_sync(0xffffffffu, be.x, 0);
    float4 m = g_mean4[lane];
    float m0 = __shfl_sync(0xffffffffu, m.x, 0);
    float inv1pm0 = 1.f / (1.f + m0);
    float mxs = (lane == 0) ? -m.x : m.x;
    float e0  = (lane == 0) ?  1.f : 0.f;
    float4 scl = load_scale(gamma4, lane);
    float inv1pb0 = 1.f / (1.f + b0);
    float bxs = (lane == 0) ? -be.x : be.x;

    int gw = blockIdx.x * 8 + warp;
    for (int p = gw; p < PIT; p += NW_FG) {
        unsigned bi = (unsigned)p * 64u + lane;
        float4 v[P];
        v[0] = __ldcs(&x4[bi]);
        v[1] = __ldcs(&x4[bi + 32u]);
        xT_P<P>(v, m, mxs, m0, inv1pm0, e0);
        float r2[2 * P];
#pragma unroll
        for (int i = 0; i < P; i++) {
            v[i].x *= scl.x; v[i].y *= scl.y; v[i].z *= scl.z; v[i].w *= scl.w;
            float4 t = v[i];
            r2[2*i]   = t.x*t.x + t.y*t.y + t.z*t.z + t.w*t.w;
            r2[2*i+1] = t.x*bxs + t.y*be.y + t.z*be.z + t.w*be.w;   // linner(t,be)
        }
        wsumP<2 * P>(r2);
#pragma unroll
        for (int i = 0; i < P; i++) {
            float rre = fmaxf(r2[2*i], 1e-8f);
            float rq  = rsqrtf(rre);
            float esc = fminf(1.f, 32.f * rq);     // euclid cap
            float coef = esc * r2[2*i+1] * inv1pb0;
            float4 t = v[i], w;
            w.x = fmaf(coef, be.x + e0, esc * t.x);
            w.y = fmaf(coef, be.y, esc * t.y);
            w.z = fmaf(coef, be.z, esc * t.z);
            w.w = fmaf(coef, be.w, esc * t.w);
            // linner(w,w) = esc^2 * re   (t0 == 0; transport preserves norm)
            float nu  = fminf(rre * rq, 32.f);
            float rnu = fmaxf(nu, 1e-4f);
            float ex  = __expf(rnu);
            float exi = __expf(-rnu);
            float ch  = 0.5f * (ex + exi);
            float shn = 0.5f * (ex - exi) / rnu;
            float4 o;
            o.x = fmaf(ch, be.x, shn * w.x);
            o.y = fmaf(ch, be.y, shn * w.y);
            o.z = fmaf(ch, be.z, shn * w.z);
            o.w = fmaf(ch, be.w, shn * w.w);
            __stcs(&out4[bi + (unsigned)i * 32u], o);
        }
    }
}

extern "C" void kernel_launch(void* const* d_in, const int* in_sizes, int n_in,
                              void* d_out, int out_size) {
    const float4* x  = (const float4*)d_in[0];
    const float4* ga = (const float4*)d_in[1];
    const float4* be = (const float4*)d_in[2];
    float4* out = (float4*)d_out;
    (void)in_sizes; (void)n_in; (void)out_size;

    k_sumS<<<BB * CHUNKS, 256>>>(x);
    k_centroid<<<1, 1024>>>(be);
    k_stats<<<GRID_STATS, 256>>>(x);
    k_final_o<<<GRID_FO, 256>>>(x, ga, out);
    k_final_g<<<GRID_FG, 256>>>(x, ga, be, out);
}

// round 9
// speedup vs baseline: 1.1598x; 1.0492x over previous
#include <cuda_runtime.h>

#define BB 64
#define SS 4096
#define DD 128
#define NPTS (BB*SS)
#define CHUNKS 16
#define PPB (SS/CHUNKS)
#define GRID_STATS 740            // 5 blocks/SM * 148 SMs, one wave
#define NW_STATS (GRID_STATS * 8)
#define GRID_FIN 592              // 4 blocks/SM * 148 SMs, one wave
#define NW_FIN (GRID_FIN * 8)

// scratch (allocation-free rule: __device__ globals)
__device__ float  g_part[CHUNKS*BB*DD]; // per-(chunk,b,d) partial sums
__device__ float4 g_mean4[DD/4];        // global Lorentz centroid
__device__ double g_fs[DD];             // per-feature sum of x_T
__device__ double g_fq[DD];             // per-feature sum of x_T^2

__device__ __forceinline__ float wsum(float v) {
#pragma unroll
    for (int o = 16; o; o >>= 1) v += __shfl_xor_sync(0xffffffffu, v, o);
    return v;
}

// 16-lane-segment reduction: 4 stages, reduces two points per warp at once
__device__ __forceinline__ float segsum(float v) {
#pragma unroll
    for (int o = 8; o; o >>= 1) v += __shfl_xor_sync(0xffffffffu, v, o);
    return v;
}
__device__ __forceinline__ void segsum2(float& a, float& b) {
#pragma unroll
    for (int o = 8; o; o >>= 1) {
        float ta = __shfl_xor_sync(0xffffffffu, a, o);
        float tb = __shfl_xor_sync(0xffffffffu, b, o);
        a += ta; b += tb;
    }
}
__device__ __forceinline__ float dot4(float4 a, float4 b) {
    return a.x*b.x + a.y*b.y + a.z*b.z + a.w*b.w;
}

// Pass 1: per-(b,chunk) sums over 256 points -> g_part (no atomics, no init)
__global__ __launch_bounds__(256) void k_sumS(const float4* __restrict__ x4) {
    int b     = blockIdx.x >> 4;
    int chunk = blockIdx.x & 15;
    int warp = threadIdx.x >> 5, lane = threadIdx.x & 31;
    const float4* base = x4 + ((size_t)b * SS + (size_t)chunk * PPB) * 32 + lane;
    float4 acc = make_float4(0.f, 0.f, 0.f, 0.f);
#pragma unroll 4
    for (int s = warp; s < PPB; s += 8) {
        float4 v = base[(size_t)s * 32];
        acc.x += v.x; acc.y += v.y; acc.z += v.z; acc.w += v.w;
    }
    __shared__ float sh[8 * 128];
    int o = warp * 128 + lane * 4;
    sh[o] = acc.x; sh[o+1] = acc.y; sh[o+2] = acc.z; sh[o+3] = acc.w;
    __syncthreads();
    if (threadIdx.x < 128) {
        float v = 0.f;
#pragma unroll
        for (int w = 0; w < 8; w++) v += sh[w * 128 + threadIdx.x];
        g_part[(chunk * BB + b) * DD + threadIdx.x] = v;
    }
}

// Pass 2 (tiny): reduce partials, centroid of per-batch centroids, zero stats
__global__ __launch_bounds__(1024) void k_centroid() {
    __shared__ float sh1[BB * DD];
    __shared__ float red[128];
    __shared__ float s_linner;
    int tid = threadIdx.x, warp = tid >> 5, lane = tid & 31;

    for (int idx = tid; idx < BB*DD; idx += 1024) {
        float s = 0.f;
#pragma unroll
        for (int c = 0; c < CHUNKS; c++) s += g_part[c * BB * DD + idx];
        sh1[idx] = s;
    }
    if (tid < DD) { g_fs[tid] = 0.0; g_fq[tid] = 0.0; }
    __syncthreads();

#pragma unroll
    for (int rep = 0; rep < 2; rep++) {
        int b = warp + rep * 32;
        float a[4];
        float lc = 0.f;
#pragma unroll
        for (int j = 0; j < 4; j++) {
            a[j] = sh1[b * 128 + lane * 4 + j] * (1.f / SS);
            float c = a[j] * a[j];
            if (lane == 0 && j == 0) c = -c;
            lc += c;
        }
        lc = wsum(lc);
        float denom = sqrtf(fmaxf(-lc, 1e-8f));
#pragma unroll
        for (int j = 0; j < 4; j++) sh1[b * 128 + lane * 4 + j] = a[j] / denom;
    }
    __syncthreads();

    float a2 = 0.f;
    if (tid < 128) {
        float s = 0.f;
        for (int b = 0; b < BB; b++) s += sh1[b * 128 + tid];
        a2 = s * (1.f / BB);
        float c = a2 * a2;
        red[tid] = (tid == 0) ? -c : c;
    }
    __syncthreads();
    for (int off = 64; off > 0; off >>= 1) {
        if (tid < off) red[tid] += red[tid + off];
        __syncthreads();
    }
    if (tid == 0) s_linner = red[0];
    __syncthreads();
    if (tid < 128) {
        float denom2 = sqrtf(fmaxf(-s_linner, 1e-8f));
        ((float*)g_mean4)[tid] = a2 / denom2;
    }
}

// Pass 3: per-feature sum / sumsq of x_T. 16-lane segments: each half-warp
// owns one point (8 features/lane as 2 float4), 2 points per warp-iteration.
__global__ __launch_bounds__(256, 5) void k_stats(const float4* __restrict__ x4) {
    constexpr int PAIRS = NPTS / 2;
    int warp = threadIdx.x >> 5, lane = threadIdx.x & 31;
    int j = lane & 15;
    unsigned offl = (unsigned)(((lane >> 4) << 5) + j);   // seg*32 + j
    float e0 = (j == 0) ? 1.f : 0.f;
    float4 mA = g_mean4[j], mB = g_mean4[j + 16];
    float m0 = ((const float*)g_mean4)[0];
    float inv1pm0 = 1.f / (1.f + m0);
    float mAxs = (j == 0) ? -mA.x : mA.x;

    float4 ssA = make_float4(0,0,0,0), ssB = make_float4(0,0,0,0);
    float4 sqA = make_float4(0,0,0,0), sqB = make_float4(0,0,0,0);
    int gw = blockIdx.x * 8 + warp;

    for (int pp = PAIRS - 1 - gw; pp >= 0; pp -= NW_STATS) {   // reverse sweep
        unsigned bi = (unsigned)pp * 64u + offl;
        float4 vA = x4[bi];
        float4 vB = x4[bi + 16u];
        // linner(x, m): feature-0 term negated via mAxs
        float dp = vA.x*mAxs + vA.y*mA.y + vA.z*mA.z + vA.w*mA.w + dot4(vB, mB);
        dp = segsum(dp);
        float x0 = __shfl_sync(0xffffffffu, vA.x, lane & 16);  // segment base lane
        float alpha  = fmaxf(-dp, 1.0f + 1e-7f);
        float uu     = fmaf(alpha, alpha, -1.0f);
        float runorm = rsqrtf(uu);
        float fac    = __logf(alpha + uu * runorm) * runorm;   // acosh(a)/|u|
        float u0     = fmaf(-alpha, m0, x0);
        float coef   = -fac * u0 * inv1pm0;                    // transp0back
        float c2     = fmaf(-fac, alpha, coef);
        float4 tA, tB;
        tA.x = fmaf(fac, vA.x, fmaf(c2, mA.x, coef * e0));
        tA.y = fmaf(fac, vA.y, c2 * mA.y);
        tA.z = fmaf(fac, vA.z, c2 * mA.z);
        tA.w = fmaf(fac, vA.w, c2 * mA.w);
        tB.x = fmaf(fac, vB.x, c2 * mB.x);
        tB.y = fmaf(fac, vB.y, c2 * mB.y);
        tB.z = fmaf(fac, vB.z, c2 * mB.z);
        tB.w = fmaf(fac, vB.w, c2 * mB.w);
        ssA.x += tA.x; ssA.y += tA.y; ssA.z += tA.z; ssA.w += tA.w;
        ssB.x += tB.x; ssB.y += tB.y; ssB.z += tB.z; ssB.w += tB.w;
        sqA.x = fmaf(tA.x, tA.x, sqA.x); sqA.y = fmaf(tA.y, tA.y, sqA.y);
        sqA.z = fmaf(tA.z, tA.z, sqA.z); sqA.w = fmaf(tA.w, tA.w, sqA.w);
        sqB.x = fmaf(tB.x, tB.x, sqB.x); sqB.y = fmaf(tB.y, tB.y, sqB.y);
        sqB.z = fmaf(tB.z, tB.z, sqB.z); sqB.w = fmaf(tB.w, tB.w, sqB.w);
    }

    // merge the two segments (same features): one xor-16 pass
    float acc[16] = {ssA.x,ssA.y,ssA.z,ssA.w, ssB.x,ssB.y,ssB.z,ssB.w,
                     sqA.x,sqA.y,sqA.z,sqA.w, sqB.x,sqB.y,sqB.z,sqB.w};
#pragma unroll
    for (int i = 0; i < 16; i++) acc[i] += __shfl_xor_sync(0xffffffffu, acc[i], 16);

    __shared__ float shs[8 * 128];
    __shared__ float shq[8 * 128];
    if (lane < 16) {
        int o = warp * 128 + j * 4;
#pragma unroll
        for (int c = 0; c < 4; c++) {
            shs[o + c]      = acc[c];
            shs[o + 64 + c] = acc[4 + c];
            shq[o + c]      = acc[8 + c];
            shq[o + 64 + c] = acc[12 + c];
        }
    }
    __syncthreads();
    if (threadIdx.x < 128) {
        float a = 0.f, b = 0.f;
#pragma unroll
        for (int w = 0; w < 8; w++) { a += shs[w*128 + threadIdx.x]; b += shq[w*128 + threadIdx.x]; }
        atomicAdd(&g_fs[threadIdx.x], (double)a);
        atomicAdd(&g_fq[threadIdx.x], (double)b);
    }
}

// per-feature scale = gamma / (sqrt(var + eps) + eps), for float4 group idx
__device__ __forceinline__ float4 load_scale(const float4* gamma4, int idx) {
    float4 g = gamma4[idx];
    float gv[4] = {g.x, g.y, g.z, g.w};
    float sv[4];
#pragma unroll
    for (int c = 0; c < 4; c++) {
        int d = idx * 4 + c;
        float mv  = (float)(g_fs[d] * (1.0 / NPTS));
        float var = (float)(g_fq[d] * (1.0 / NPTS)) - mv * mv;
        float std = sqrtf(fmaxf(var, 0.f) + 1e-5f);
        sv[c] = gv[c] / (std + 1e-5f);
    }
    return make_float4(sv[0], sv[1], sv[2], sv[3]);
}

// Pass 4: scale, euclid cap, transp0(beta), expmap(beta). 16-lane segments.
// t0 == 0 identically; beta==origin => transp0 = identity.
__global__ __launch_bounds__(256) void k_final(const float4* __restrict__ x4,
                                               const float4* __restrict__ gamma4,
                                               const float4* __restrict__ beta4,
                                               float4* __restrict__ out4) {
    constexpr int PAIRS = NPTS / 2;
    int warp = threadIdx.x >> 5, lane = threadIdx.x & 31;
    int j = lane & 15;
    unsigned offl = (unsigned)(((lane >> 4) << 5) + j);
    float e0 = (j == 0) ? 1.f : 0.f;
    float4 mA = g_mean4[j], mB = g_mean4[j + 16];
    float m0 = ((const float*)g_mean4)[0];
    float inv1pm0 = 1.f / (1.f + m0);
    float mAxs = (j == 0) ? -mA.x : mA.x;
    float4 sclA = load_scale(gamma4, j);
    float4 sclB = load_scale(gamma4, j + 16);
    float4 beA = beta4[j], beB = beta4[j + 16];
    float b0 = __shfl_sync(0xffffffffu, beA.x, lane & 16);
    float inv1pb0 = 1.f / (1.f + b0);
    float beAxs = (j == 0) ? -beA.x : beA.x;
    float bsq = segsum(dot4(beA, beA) + dot4(beB, beB));
    bool is_origin = (b0 == 1.0f) && (bsq - b0 * b0 <= 0.0f);

    int gw = blockIdx.x * 8 + warp;
    for (int pp = gw; pp < PAIRS; pp += NW_FIN) {   // forward sweep (L2 tail of k_stats)
        unsigned bi = (unsigned)pp * 64u + offl;
        float4 vA = __ldcs(&x4[bi]);
        float4 vB = __ldcs(&x4[bi + 16u]);
        float dp = vA.x*mAxs + vA.y*mA.y + vA.z*mA.z + vA.w*mA.w + dot4(vB, mB);
        dp = segsum(dp);
        float x0 = __shfl_sync(0xffffffffu, vA.x, lane & 16);
        float alpha  = fmaxf(-dp, 1.0f + 1e-7f);
        float uu     = fmaf(alpha, alpha, -1.0f);
        float runorm = rsqrtf(uu);
        float fac    = __logf(alpha + uu * runorm) * runorm;
        float u0     = fmaf(-alpha, m0, x0);
        float coef   = -fac * u0 * inv1pm0;
        float c2     = fmaf(-fac, alpha, coef);
        float4 tA, tB;
        tA.x = sclA.x * fmaf(fac, vA.x, fmaf(c2, mA.x, coef * e0));
        tA.y = sclA.y * fmaf(fac, vA.y, c2 * mA.y);
        tA.z = sclA.z * fmaf(fac, vA.z, c2 * mA.z);
        tA.w = sclA.w * fmaf(fac, vA.w, c2 * mA.w);
        tB.x = sclB.x * fmaf(fac, vB.x, c2 * mB.x);
        tB.y = sclB.y * fmaf(fac, vB.y, c2 * mB.y);
        tB.z = sclB.z * fmaf(fac, vB.z, c2 * mB.z);
        tB.w = sclB.w * fmaf(fac, vB.w, c2 * mB.w);
        float re = dot4(tA, tA) + dot4(tB, tB);      // euclid norm^2

        float4 oA, oB;
        if (is_origin) {
            re = segsum(re);
            float rre = fmaxf(re, 1e-8f);
            float rq  = rsqrtf(rre);
            float en  = rre * rq;                    // ||t||
            float nu  = fminf(en, 32.f);             // esc * ||t||
            float ex  = __expf(nu);
            float exi = __expf(-nu);
            float ch  = 0.5f * (ex + exi);
            float sf  = 0.5f * (ex - exi) / en;      // esc * sinh(nu)/nu
            oA.x = fmaf(sf, tA.x, ch * e0);
            oA.y = sf * tA.y; oA.z = sf * tA.z; oA.w = sf * tA.w;
            oB.x = sf * tB.x; oB.y = sf * tB.y; oB.z = sf * tB.z; oB.w = sf * tB.w;
        } else {
            float rb = tA.x*beAxs + tA.y*beA.y + tA.z*beA.z + tA.w*beA.w + dot4(tB, beB);
            segsum2(re, rb);
            float rre = fmaxf(re, 1e-8f);
            float rq  = rsqrtf(rre);
            float esc = fminf(1.f, 32.f * rq);       // euclid cap
            float coefb = esc * rb * inv1pb0;        // transp0(beta)
            float4 wA, wB;
            wA.x = fmaf(coefb, beA.x + e0, esc * tA.x);
            wA.y = fmaf(coefb, beA.y, esc * tA.y);
            wA.z = fmaf(coefb, beA.z, esc * tA.z);
            wA.w = fmaf(coefb, beA.w, esc * tA.w);
            wB.x = fmaf(coefb, beB.x, esc * tB.x);
            wB.y = fmaf(coefb, beB.y, esc * tB.y);
            wB.z = fmaf(coefb, beB.z, esc * tB.z);
            wB.w = fmaf(coefb, beB.w, esc * tB.w);
            // linner(w,w) = esc^2 * re  (t0 == 0; transport preserves norm)
            float nu  = fminf(rre * rq, 32.f);
            float rnu = fmaxf(nu, 1e-4f);
            float ex  = __expf(rnu);
            float exi = __expf(-rnu);
            float ch  = 0.5f * (ex + exi);
            float shn = 0.5f * (ex - exi) / rnu;
            oA.x = fmaf(ch, beA.x, shn * wA.x);
            oA.y = fmaf(ch, beA.y, shn * wA.y);
            oA.z = fmaf(ch, beA.z, shn * wA.z);
            oA.w = fmaf(ch, beA.w, shn * wA.w);
            oB.x = fmaf(ch, beB.x, shn * wB.x);
            oB.y = fmaf(ch, beB.y, shn * wB.y);
            oB.z = fmaf(ch, beB.z, shn * wB.z);
            oB.w = fmaf(ch, beB.w, shn * wB.w);
        }
        __stcs(&out4[bi], oA);
        __stcs(&out4[bi + 16u], oB);
    }
}

extern "C" void kernel_launch(void* const* d_in, const int* in_sizes, int n_in,
                              void* d_out, int out_size) {
    const float4* x  = (const float4*)d_in[0];
    const float4* ga = (const float4*)d_in[1];
    const float4* be = (const float4*)d_in[2];
    float4* out = (float4*)d_out;
    (void)in_sizes; (void)n_in; (void)out_size;

    k_sumS<<<BB * CHUNKS, 256>>>(x);
    k_centroid<<<1, 1024>>>();
    k_stats<<<GRID_STATS, 256>>>(x);
    k_final<<<GRID_FIN, 256>>>(x, ga, be, out);
}